// round 8
// baseline (speedup 1.0000x reference)
#include <cuda_runtime.h>
#include <math.h>
#include <stdint.h>

#ifndef M_PI
#define M_PI 3.14159265358979323846
#endif

#define S_LEN 128
#define B_SZ  128
#define T_OUT 12
#define NSAMP (S_LEN * B_SZ)   // 16384
#define N_OPS 30

#define NBLK       148
#define NLSTM_BLK  8            // 8 blocks x 16 warps = 128 lstm warps
#define NWORK_BLK  (NBLK - NLSTM_BLK)   // 140
#define NWARP_WORK (NWORK_BLK * 16)     // 2240
#define THREADS    512
#define N_ITEMS    4096         // embed items (4 samples each), s-major

// ---------------------------------------------------------------------------
// Scratch + progress counters (device globals; no allocation allowed)
// ---------------------------------------------------------------------------
__device__ float g_zx[NSAMP * 32];      // [s*B+b][g*8+q]
__device__ float g_h [NSAMP * 8];       // [s*B+b][h]
__device__ unsigned g_emb_chunk[8];     // 512 items per 16-s chunk
__device__ unsigned g_lstm_s[S_LEN];    // 128 warp-arrivals per s

struct QOps {
    int   kind[N_OPS];   // 0=rx, 1=ry, 2=rz, 3=cnot
    int   pa[N_OPS];     // bit position of wire (rot) / control (cnot); <5 lane, >=5 k
    int   pb[N_OPS];     // bit position of target (cnot)
    float c[N_OPS];      // cos(theta/2)
    float s[N_OPS];      // sin(theta/2)
    int   ord[8];        // ord[j] = wire living at bit position j
};

// ---------------------------------------------------------------------------
// Sync + math helpers
// ---------------------------------------------------------------------------
__device__ __forceinline__ unsigned ld_acq(const unsigned* p) {
    unsigned v;
    asm volatile("ld.acquire.gpu.global.u32 %0, [%1];" : "=r"(v) : "l"(p));
    return v;
}
__device__ __forceinline__ void red_rel(unsigned* p) {
    asm volatile("red.release.gpu.global.add.u32 [%0], 1;" :: "l"(p) : "memory");
}
__device__ __forceinline__ float fast_sigmoid(float x) {
    return __fdividef(1.f, 1.f + __expf(-x));
}
__device__ __forceinline__ float fast_tanh(float x) {
    x = fminf(fmaxf(x, -15.f), 15.f);
    float t = __expf(2.f * x);
    return __fdividef(t - 1.f, t + 1.f);
}

// ---------------------------------------------------------------------------
// Init kernel: zero progress counters (every call / graph replay)
// ---------------------------------------------------------------------------
__global__ void k_init() {
    int t = threadIdx.x;
    if (t < 8)      g_emb_chunk[t] = 0;
    if (t < S_LEN)  g_lstm_s[t]    = 0;
}

// ---------------------------------------------------------------------------
// LSTM warp: one warp per batch element b. Horner form for the gate proj.
// ---------------------------------------------------------------------------
__device__ void lstm_warp(int b, int l,
                          const float* __restrict__ Win,
                          const float* __restrict__ Wout,
                          const float* __restrict__ b_out)
{
    const unsigned FULL = 0xffffffffu;
    int g = l >> 3, h = l & 7;

    float winh[8], wo[8];
    #pragma unroll
    for (int j = 0; j < 8; j++) {
        winh[j] = Win[l * 72 + 64 + j];
        wo[j]   = Wout[(g * 8 + h) * 8 + j];
    }
    float bo = b_out[g * 8 + h];

    float cst = 0.f, hh = 0.f, zbuf = 0.f;
    for (int s = 0; s < S_LEN; s++) {
        float z;
        if ((s & 15) == 0) {
            unsigned* ch = &g_emb_chunk[s >> 4];
            while (ld_acq(ch) < 512u) __nanosleep(64);
            z = __ldcg(&g_zx[(s * B_SZ + b) * 32 + l]);
        } else {
            z = zbuf;
        }
        if ((s & 15) != 15)    // s+1 is inside the already-confirmed chunk
            zbuf = __ldcg(&g_zx[((s + 1) * B_SZ + b) * 32 + l]);

        #pragma unroll
        for (int j = 0; j < 8; j++)
            z = fmaf(__shfl_sync(FULL, hh, j), winh[j], z);

        float cz = __cosf(z);
        float cj[8];
        #pragma unroll
        for (int j = 0; j < 8; j++)
            cj[j] = __shfl_sync(FULL, cz, (g << 3) | j);

        // pre = bo + c0*(W0 + c1*(W1 + ... + c7*W7)) == sum_q W_q * cumprod_q
        float t = wo[7];
        #pragma unroll
        for (int j = 6; j >= 0; j--)
            t = fmaf(cj[j + 1], t, wo[j]);
        float pre = fmaf(cj[0], t, bo);

        float pf = __shfl_sync(FULL, pre, h);
        float pi = __shfl_sync(FULL, pre, 8  | h);
        float pg = __shfl_sync(FULL, pre, 16 | h);
        float po = __shfl_sync(FULL, pre, 24 | h);

        float fg = fast_sigmoid(pf);
        float ig = fast_sigmoid(pi);
        float gg = fast_tanh(pg);
        float og = fast_sigmoid(po);

        cst = fmaf(fg, cst, ig * gg);
        hh  = og * fast_tanh(cst);

        if (l < 8) g_h[(s * B_SZ + b) * 8 + l] = hh;
        __syncwarp();
        if (l == 0) red_rel(&g_lstm_s[s]);   // release: h(s, b) published
    }
}

// ---------------------------------------------------------------------------
// QFC per sample r (s-major: s = r>>7, b = r&127). Register statevector.
// ---------------------------------------------------------------------------
#define RXP(i,j) do { float nx0=c*ax[i]+sn*ay[j], ny0=c*ay[i]-sn*ax[j]; \
                      float nx1=c*ax[j]+sn*ay[i], ny1=c*ay[j]-sn*ax[i]; \
                      ax[i]=nx0; ay[i]=ny0; ax[j]=nx1; ay[j]=ny1; } while(0)
#define RYP(i,j) do { float nx0=c*ax[i]-sn*ax[j], ny0=c*ay[i]-sn*ay[j]; \
                      float nx1=sn*ax[i]+c*ax[j], ny1=sn*ay[i]+c*ay[j]; \
                      ax[i]=nx0; ay[i]=ny0; ax[j]=nx1; ay[j]=ny1; } while(0)
#define SWP(i,j) do { float tx=ax[i]; ax[i]=ax[j]; ax[j]=tx; \
                      float ty=ay[i]; ay[i]=ay[j]; ay[j]=ty; } while(0)
#define PAIRS_SWITCH(kb, APPLY) \
    switch (kb) { \
      case 0:  APPLY(0,1); APPLY(2,3); APPLY(4,5); APPLY(6,7); break; \
      case 1:  APPLY(0,2); APPLY(1,3); APPLY(4,6); APPLY(5,7); break; \
      default: APPLY(0,4); APPLY(1,5); APPLY(2,6); APPLY(3,7); break; \
    }

__device__ void qfc_sample(int r, int l, const QOps& ops,
                           const float* __restrict__ phiq,
                           const float* __restrict__ Whead,
                           const float* __restrict__ b_head,
                           float* __restrict__ out)
{
    const unsigned FULL = 0xffffffffu;
    int s = r >> 7, b = r & 127;

    const float* th = &g_h[(s * B_SZ + b) * 8];
    float cw[8], sw[8];
    #pragma unroll
    for (int j = 0; j < 8; j++) {
        float v = __ldcg(&th[ops.ord[j]]);       // wire at bit position j
        __sincosf(0.5f * v, &sw[j], &cw[j]);
    }

    // Product-state init (bit position j<5 -> lane bit j, j>=5 -> k bit j-5)
    float base = 1.f;
    #pragma unroll
    for (int j = 0; j < 5; j++)
        base *= ((l >> j) & 1) ? sw[j] : cw[j];

    float ax[8], ay[8];
    #pragma unroll
    for (int k = 0; k < 8; k++) {
        float t = ((k      & 1) ? sw[5] : cw[5]) *
                  (((k >> 1) & 1) ? sw[6] : cw[6]) *
                  (((k >> 2) & 1) ? sw[7] : cw[7]);
        ax[k] = base * t;
        ay[k] = 0.f;
    }

    // 30 random ops + 8 trainable RX(phiq) — uniform control flow
    for (int op = 0; op < N_OPS + 8; op++) {
        int kind, pa, pb_;
        float c, sn;
        if (op < N_OPS) {
            kind = ops.kind[op];
            pa   = ops.pa[op];
            pb_  = ops.pb[op];
            c    = ops.c[op];
            sn   = ops.s[op];
        } else {
            int e = op - N_OPS;
            kind = 0; pa = e; pb_ = 0;
            __sincosf(0.5f * phiq[ops.ord[e]], &sn, &c);
        }

        if (kind == 3) {                              // ---- CNOT ----
            int pc = pa, pt = pb_;
            if (pc < 5 && pt < 5) {
                unsigned m = 1u << pt;
                bool ctl = (l >> pc) & 1;
                #pragma unroll
                for (int k = 0; k < 8; k++) {
                    float qx = __shfl_xor_sync(FULL, ax[k], m);
                    float qy = __shfl_xor_sync(FULL, ay[k], m);
                    if (ctl) { ax[k] = qx; ay[k] = qy; }
                }
            } else if (pc < 5) {
                bool ctl = (l >> pc) & 1;
                if (ctl) { PAIRS_SWITCH(pt - 5, SWP); }
            } else if (pt < 5) {
                unsigned m = 1u << pt;
                int ckb = pc - 5;
                #pragma unroll
                for (int k = 0; k < 8; k++) {
                    float qx = __shfl_xor_sync(FULL, ax[k], m);
                    float qy = __shfl_xor_sync(FULL, ay[k], m);
                    if ((k >> ckb) & 1) { ax[k] = qx; ay[k] = qy; }
                }
            } else {
                int ckb = pc - 5, tkb = pt - 5;
                switch (ckb * 4 + tkb) {
                  case 1:  SWP(1,3); SWP(5,7); break;
                  case 2:  SWP(1,5); SWP(3,7); break;
                  case 4:  SWP(2,3); SWP(6,7); break;
                  case 6:  SWP(2,6); SWP(3,7); break;
                  case 8:  SWP(4,5); SWP(6,7); break;
                  default: SWP(4,6); SWP(5,7); break;
                }
            }
        } else if (kind == 2) {                       // ---- RZ ----
            if (pa < 5) {
                float sg = ((l >> pa) & 1) ? -sn : sn;
                #pragma unroll
                for (int k = 0; k < 8; k++) {
                    float x = ax[k], y = ay[k];
                    ax[k] = c * x + sg * y;
                    ay[k] = c * y - sg * x;
                }
            } else {
                int kb = pa - 5;
                #pragma unroll
                for (int k = 0; k < 8; k++) {
                    float sg = ((k >> kb) & 1) ? -sn : sn;
                    float x = ax[k], y = ay[k];
                    ax[k] = c * x + sg * y;
                    ay[k] = c * y - sg * x;
                }
            }
        } else if (kind == 1) {                       // ---- RY ----
            if (pa < 5) {
                unsigned m = 1u << pa;
                float sg = ((l >> pa) & 1) ? sn : -sn;
                #pragma unroll
                for (int k = 0; k < 8; k++) {
                    float px = __shfl_xor_sync(FULL, ax[k], m);
                    float py = __shfl_xor_sync(FULL, ay[k], m);
                    ax[k] = c * ax[k] + sg * px;
                    ay[k] = c * ay[k] + sg * py;
                }
            } else {
                PAIRS_SWITCH(pa - 5, RYP);
            }
        } else {                                      // ---- RX ----
            if (pa < 5) {
                unsigned m = 1u << pa;
                #pragma unroll
                for (int k = 0; k < 8; k++) {
                    float px = __shfl_xor_sync(FULL, ax[k], m);
                    float py = __shfl_xor_sync(FULL, ay[k], m);
                    ax[k] = c * ax[k] + sn * py;
                    ay[k] = c * ay[k] - sn * px;
                }
            } else {
                PAIRS_SWITCH(pa - 5, RXP);
            }
        }
    }

    // Measure <Z> per bit position
    float pb4[8];
    #pragma unroll
    for (int k = 0; k < 8; k++) pb4[k] = ax[k] * ax[k] + ay[k] * ay[k];

    float P = ((pb4[0] + pb4[1]) + (pb4[2] + pb4[3])) +
              ((pb4[4] + pb4[5]) + (pb4[6] + pb4[7]));
    float mb0 = (pb4[0] + pb4[2] + pb4[4] + pb4[6]) - (pb4[1] + pb4[3] + pb4[5] + pb4[7]);
    float mb1 = (pb4[0] + pb4[1] + pb4[4] + pb4[5]) - (pb4[2] + pb4[3] + pb4[6] + pb4[7]);
    float mb2 = (pb4[0] + pb4[1] + pb4[2] + pb4[3]) - (pb4[4] + pb4[5] + pb4[6] + pb4[7]);

    float z[8];
    #pragma unroll
    for (int j = 0; j < 5; j++)
        z[j] = ((l >> j) & 1) ? -P : P;
    z[5] = mb0; z[6] = mb1; z[7] = mb2;

    #pragma unroll
    for (int off = 16; off >= 1; off >>= 1) {
        #pragma unroll
        for (int j = 0; j < 8; j++)
            z[j] += __shfl_xor_sync(FULL, z[j], off);
    }

    // Head + log_softmax (lanes 0..11); permutation folded into Whead index
    float lg = -INFINITY;
    if (l < T_OUT) {
        lg = b_head[l];
        #pragma unroll
        for (int j = 0; j < 8; j++)
            lg = fmaf(Whead[l * 8 + ops.ord[j]], z[j], lg);
    }
    float m = lg;
    #pragma unroll
    for (int off = 16; off >= 1; off >>= 1)
        m = fmaxf(m, __shfl_xor_sync(FULL, m, off));
    float e = (l < T_OUT) ? expf(lg - m) : 0.f;
    float se = e;
    #pragma unroll
    for (int off = 16; off >= 1; off >>= 1)
        se += __shfl_xor_sync(FULL, se, off);

    if (l < T_OUT)
        out[(b * S_LEN + s) * T_OUT + l] = lg - m - logf(se);
}

// ---------------------------------------------------------------------------
// Fused kernel
// ---------------------------------------------------------------------------
__global__ void __launch_bounds__(THREADS, 1) k_fused(
        const float* __restrict__ emb,
        const float* __restrict__ Win,
        const float* __restrict__ b_in,
        const float* __restrict__ phi,
        const float* __restrict__ Wout,
        const float* __restrict__ b_out,
        const float* __restrict__ phiq,
        const float* __restrict__ Whead,
        const float* __restrict__ b_head,
        const void*  __restrict__ sent_raw,
        float* __restrict__ out,
        QOps ops)
{
    int tid = threadIdx.x, wid = tid >> 5, l = tid & 31;

    if (blockIdx.x < NLSTM_BLK) {
        int b = blockIdx.x * 16 + wid;      // 8 blocks x 16 warps = 128
        lstm_warp(b, l, Win, Wout, b_out);
        return;
    }

    // ---- work blocks: embed phase then qfc phase ----
    __shared__ float winT[64 * 32];         // [e][l]
    __shared__ float bp[32];
    for (int k = tid; k < 64 * 32; k += THREADS) {
        int e = k >> 5, ll = k & 31;
        winT[k] = Win[ll * 72 + e];
    }
    if (tid < 32) bp[tid] = b_in[tid] + phi[tid];
    __syncthreads();

    // dtype sniff: int64 sentence has all-zero high words (tokens < 30000)
    const int* si = (const int*)sent_raw;
    bool is64 = true;
    #pragma unroll
    for (int k = 0; k < 16; k++)
        if (si[2 * k + 1] != 0) is64 = false;

    int wq = (blockIdx.x - NLSTM_BLK) * 16 + wid;   // 0..2239

    // ---- embed: items of 4 s-major samples ----
    for (int item = wq; item < N_ITEMS; item += NWARP_WORK) {
        int sm0 = item * 4;
        long long t0 = is64 ? ((const long long*)sent_raw)[sm0 + 0] : (long long)si[sm0 + 0];
        long long t1 = is64 ? ((const long long*)sent_raw)[sm0 + 1] : (long long)si[sm0 + 1];
        long long t2 = is64 ? ((const long long*)sent_raw)[sm0 + 2] : (long long)si[sm0 + 2];
        long long t3 = is64 ? ((const long long*)sent_raw)[sm0 + 3] : (long long)si[sm0 + 3];
        const float4* e0 = (const float4*)(emb + t0 * 64);
        const float4* e1 = (const float4*)(emb + t1 * 64);
        const float4* e2 = (const float4*)(emb + t2 * 64);
        const float4* e3 = (const float4*)(emb + t3 * 64);

        float a0 = bp[l], a1 = a0, a2 = a0, a3 = a0;
        #pragma unroll
        for (int e4 = 0; e4 < 16; e4++) {
            float4 v0 = e0[e4], v1 = e1[e4], v2 = e2[e4], v3 = e3[e4];
            float w0 = winT[(e4 * 4 + 0) * 32 + l];
            float w1 = winT[(e4 * 4 + 1) * 32 + l];
            float w2 = winT[(e4 * 4 + 2) * 32 + l];
            float w3 = winT[(e4 * 4 + 3) * 32 + l];
            a0 = fmaf(v0.x, w0, fmaf(v0.y, w1, fmaf(v0.z, w2, fmaf(v0.w, w3, a0))));
            a1 = fmaf(v1.x, w0, fmaf(v1.y, w1, fmaf(v1.z, w2, fmaf(v1.w, w3, a1))));
            a2 = fmaf(v2.x, w0, fmaf(v2.y, w1, fmaf(v2.z, w2, fmaf(v2.w, w3, a2))));
            a3 = fmaf(v3.x, w0, fmaf(v3.y, w1, fmaf(v3.z, w2, fmaf(v3.w, w3, a3))));
        }
        g_zx[(sm0 + 0) * 32 + l] = a0;
        g_zx[(sm0 + 1) * 32 + l] = a1;
        g_zx[(sm0 + 2) * 32 + l] = a2;
        g_zx[(sm0 + 3) * 32 + l] = a3;
        __syncwarp();
        if (l == 0) red_rel(&g_emb_chunk[item >> 9]);   // 512 items per chunk
    }

    // ---- qfc: s-major samples ----
    for (int r = wq; r < NSAMP; r += NWARP_WORK) {
        int s = r >> 7;
        unsigned* flag = &g_lstm_s[s];
        while (ld_acq(flag) < (unsigned)B_SZ) __nanosleep(128);
        qfc_sample(r, l, ops, phiq, Whead, b_head, out);
    }
}

// ---------------------------------------------------------------------------
// Host: numpy-legacy MT19937 (RandomState(1234)) -> ops + wire permutation
// ---------------------------------------------------------------------------
namespace {

struct MT19937 {
    uint32_t mt[624];
    int mti;
    void seed(uint32_t s) {
        mt[0] = s;
        for (int i = 1; i < 624; i++)
            mt[i] = 1812433253u * (mt[i - 1] ^ (mt[i - 1] >> 30)) + (uint32_t)i;
        mti = 624;
    }
    uint32_t next() {
        if (mti >= 624) {
            for (int k = 0; k < 624; k++) {
                uint32_t y = (mt[k] & 0x80000000u) | (mt[(k + 1) % 624] & 0x7fffffffu);
                mt[k] = mt[(k + 397) % 624] ^ (y >> 1) ^ ((y & 1u) ? 0x9908b0dfu : 0u);
            }
            mti = 0;
        }
        uint32_t y = mt[mti++];
        y ^= y >> 11;
        y ^= (y << 7)  & 0x9d2c5680u;
        y ^= (y << 15) & 0xefc60000u;
        y ^= y >> 18;
        return y;
    }
    uint32_t randint(uint32_t n) {
        uint32_t mx = n - 1;
        if (mx == 0) return 0;
        uint32_t mask = mx;
        mask |= mask >> 1; mask |= mask >> 2; mask |= mask >> 4;
        mask |= mask >> 8; mask |= mask >> 16;
        uint32_t v;
        do { v = next() & mask; } while (v > mx);
        return v;
    }
    double rdouble() {
        uint32_t a = next() >> 5, b2 = next() >> 6;
        return (a * 67108864.0 + b2) / 9007199254740992.0;
    }
};

void build_ops(QOps& o) {
    int kind[N_OPS], wa[N_OPS], wb[N_OPS];
    float cc[N_OPS], ss[N_OPS];

    MT19937 mt;
    mt.seed(1234u);
    int freq[8] = {0};
    for (int n = 0; n < N_OPS; n++) {
        uint32_t k = mt.randint(4);
        if (k == 3) {
            int c = (int)mt.randint(8);
            int t = (int)mt.randint(7);
            if (t >= c) t++;
            kind[n] = 3; wa[n] = c; wb[n] = t;
            cc[n] = 0.f; ss[n] = 0.f;
            freq[c]++; freq[t]++;
        } else {
            int w = (int)mt.randint(8);
            double ang = mt.rdouble() * (2.0 * M_PI);
            float angf = (float)ang;
            kind[n] = (int)(k % 3); wa[n] = w; wb[n] = 0;
            cc[n] = cosf(angf * 0.5f);
            ss[n] = sinf(angf * 0.5f);
            freq[w]++;
        }
    }

    // Wire -> bit position: 3 hottest wires get k-bit positions (5,6,7).
    int order[8] = {0, 1, 2, 3, 4, 5, 6, 7};
    for (int i = 0; i < 8; i++)           // stable selection sort by freq desc
        for (int j = i + 1; j < 8; j++)
            if (freq[order[j]] > freq[order[i]]) {
                int t = order[i]; order[i] = order[j]; order[j] = t;
            }
    int pos[8];
    for (int j = 0; j < 3; j++) { o.ord[5 + j] = order[j]; pos[order[j]] = 5 + j; }
    for (int j = 0; j < 5; j++) { o.ord[j] = order[3 + j]; pos[order[3 + j]] = j; }

    for (int n = 0; n < N_OPS; n++) {
        o.kind[n] = kind[n];
        o.pa[n]   = pos[wa[n]];
        o.pb[n]   = (kind[n] == 3) ? pos[wb[n]] : 0;
        o.c[n]    = cc[n];
        o.s[n]    = ss[n];
    }
}

} // namespace

// ---------------------------------------------------------------------------
extern "C" void kernel_launch(void* const* d_in, const int* in_sizes, int n_in,
                              void* d_out, int out_size)
{
    const float* emb    = (const float*)d_in[0];
    const float* Win    = (const float*)d_in[1];
    const float* b_in   = (const float*)d_in[2];
    const float* phi    = (const float*)d_in[3];
    const float* Wout   = (const float*)d_in[4];
    const float* b_out  = (const float*)d_in[5];
    const float* phiq   = (const float*)d_in[6];
    const float* Whead  = (const float*)d_in[7];
    const float* b_head = (const float*)d_in[8];
    const void*  sent   = (const void*)d_in[9];

    QOps ops;
    build_ops(ops);   // deterministic, recomputed every call

    k_init <<<1, 128>>>();
    k_fused<<<NBLK, THREADS>>>(emb, Win, b_in, phi, Wout, b_out,
                               phiq, Whead, b_head, sent,
                               (float*)d_out, ops);
}